// round 1
// baseline (speedup 1.0000x reference)
#include <cuda_runtime.h>
#include <cstdint>

#define W_IMG 512
#define H_IMG 512
#define HW    (512*512)
#define NB    4
#define NTAPS 25
#define EPS   1e-5f

#define TILE_W 128
#define TILE_H 16
#define BX 32
#define BY 16
#define PPT 4
#define HALO 2
#define SM_W (TILE_W + 2*HALO)   // 132
#define SM_H (TILE_H + 2*HALO)   // 20

// scratch (no allocs allowed)
__device__ unsigned int g_gray_bits[NB];
__device__ double g_accA;
__device__ double g_accB;

__global__ void init_kernel() {
    if (threadIdx.x == 0) {
        g_accA = 0.0;
        g_accB = 0.0;
        for (int i = 0; i < NB; i++) g_gray_bits[i] = 0u;  // 0.0f bits
    }
}

// per-batch max of hdr_original_gray (values >= 0, so uint compare == float compare)
__global__ void graymax_kernel(const float* __restrict__ gray) {
    const int b     = blockIdx.x >> 6;   // 64 blocks per batch
    const int chunk = blockIdx.x & 63;
    const int t     = threadIdx.x;       // 256 threads
    const float4* p4 = reinterpret_cast<const float4*>(gray + (size_t)b * HW);
    float m = 0.0f;
    const int base = chunk * 1024;       // float4 units; 1024 float4 per chunk
#pragma unroll
    for (int k = 0; k < 4; k++) {
        float4 v = p4[base + t + k * 256];
        m = fmaxf(m, fmaxf(fmaxf(v.x, v.y), fmaxf(v.z, v.w)));
    }
#pragma unroll
    for (int o = 16; o > 0; o >>= 1)
        m = fmaxf(m, __shfl_down_sync(0xFFFFFFFFu, m, o));
    __shared__ float red[8];
    if ((t & 31) == 0) red[t >> 5] = m;
    __syncthreads();
    if (t < 8) {
        m = red[t];
#pragma unroll
        for (int o = 4; o > 0; o >>= 1)
            m = fmaxf(m, __shfl_down_sync(0xFFu, m, o));
        if (t == 0) atomicMax(&g_gray_bits[b], __float_as_uint(m));
    }
}

__global__ __launch_bounds__(BX * BY, 1)
void intensity_loss_main(const float* __restrict__ fake,
                         const float* __restrict__ gamma_hdr,
                         const float* __restrict__ hdr_im,
                         const float* __restrict__ r_weights,
                         const float* __restrict__ f_factors) {
    __shared__ __align__(16) float sf[SM_H * SM_W];
    __shared__ __align__(16) float sg[SM_H * SM_W];
    __shared__ __align__(16) float sh[SM_H * SM_W];
    __shared__ float redA[16], redB[16];

    const int b     = blockIdx.z;
    const int wbase = blockIdx.x * TILE_W;
    const int hbase = blockIdx.y * TILE_H;
    const int tid   = threadIdx.y * BX + threadIdx.x;

    const float ff   = f_factors[b];
    const float expo = 1.0f - ff;
    const float gmax = __uint_as_float(g_gray_bits[b]);
    const float cobj = gmax / ff;   // ALPHA = 1

    const float* fp = fake      + (size_t)b * HW;
    const float* gp = gamma_hdr + (size_t)b * HW;
    const float* hp = hdr_im    + (size_t)b * HW;

    // ---- stage tile + halo into shared (zero-pad OOB); hdr gets pow applied here ----
    for (int i = tid; i < SM_H * SM_W; i += BX * BY) {
        const int r  = i / SM_W;
        const int c  = i - r * SM_W;
        const int gh = hbase + r - HALO;
        const int gw = wbase + c - HALO;
        float vf = 0.0f, vg = 0.0f, vh = 0.0f;
        if (gh >= 0 && gh < H_IMG && gw >= 0 && gw < W_IMG) {
            const int gi = gh * W_IMG + gw;
            vf = fp[gi];
            vg = gp[gi];
            vh = __powf(hp[gi], expo);
        }
        sf[i] = vf; sg[i] = vg; sh[i] = vh;
    }
    __syncthreads();

    // ---- per-thread: 4 consecutive pixels along W ----
    const int lw  = threadIdx.x * PPT;       // local col of first pixel
    const int lh  = threadIdx.y;             // local row
    const int gw0 = wbase + lw;
    const int gh  = hbase + lh;

    const float* rwp = r_weights + (size_t)b * NTAPS * HW + (size_t)gh * W_IMG + gw0;

    float s1f[PPT] = {0,0,0,0}, s2f[PPT] = {0,0,0,0};
    float s1g[PPT] = {0,0,0,0}, s2g[PPT] = {0,0,0,0};
    float s1h[PPT] = {0,0,0,0}, ws [PPT] = {0,0,0,0};

#pragma unroll
    for (int di = 0; di < 5; di++) {
        const int rowoff = (lh + di) * SM_W + lw;   // 16B-aligned (lw%4==0, SM_W%4==0)
        const float4 f0 = *reinterpret_cast<const float4*>(&sf[rowoff]);
        const float4 f1 = *reinterpret_cast<const float4*>(&sf[rowoff + 4]);
        const float4 g0 = *reinterpret_cast<const float4*>(&sg[rowoff]);
        const float4 g1 = *reinterpret_cast<const float4*>(&sg[rowoff + 4]);
        const float4 h0 = *reinterpret_cast<const float4*>(&sh[rowoff]);
        const float4 h1 = *reinterpret_cast<const float4*>(&sh[rowoff + 4]);
        const float xf[8] = {f0.x, f0.y, f0.z, f0.w, f1.x, f1.y, f1.z, f1.w};
        const float xg[8] = {g0.x, g0.y, g0.z, g0.w, g1.x, g1.y, g1.z, g1.w};
        const float xh[8] = {h0.x, h0.y, h0.z, h0.w, h1.x, h1.y, h1.z, h1.w};
#pragma unroll
        for (int dj = 0; dj < 5; dj++) {
            const float4 rw4 = *reinterpret_cast<const float4*>(rwp + (size_t)(di * 5 + dj) * HW);
            const float rwa[PPT] = {rw4.x, rw4.y, rw4.z, rw4.w};
#pragma unroll
            for (int l = 0; l < PPT; l++) {
                const float w = rwa[l];
                ws[l] += w;
                const float a = xf[dj + l];
                s1f[l] = fmaf(w, a, s1f[l]);
                s2f[l] = fmaf(w * a, a, s2f[l]);
                const float gq = xg[dj + l];
                s1g[l] = fmaf(w, gq, s1g[l]);
                s2g[l] = fmaf(w * gq, gq, s2g[l]);
                const float hq = xh[dj + l];
                s1h[l] = fmaf(w, hq, s1h[l]);
            }
        }
    }

    // ---- epilogue: per-pixel scalar, accumulate two sums ----
    float accA = 0.0f, accB = 0.0f;
#pragma unroll
    for (int l = 0; l < PPT; l++) {
        const float inv = 1.0f / ws[l];
        const float muf = s1f[l] * inv;
        const float vrf = fmaxf(s2f[l] * inv - muf * muf, 0.0f);
        const float stdf = sqrtf(vrf + EPS);
        const float mug = s1g[l] * inv;
        const float vrg = fmaxf(s2g[l] * inv - mug * mug, 0.0f);
        const float stdg = sqrtf(vrg + EPS);
        const float muh = s1h[l] * inv;
        const float obj = cobj * stdg * (muh + EPS);
        const float r   = 1.0f - stdf / (stdf + obj);
        const float wblf = ws[l] - 1.0f;
        accA = fmaf(r, wblf, accA);
        accB += wblf;
    }

    // ---- block reduction ----
#pragma unroll
    for (int o = 16; o > 0; o >>= 1) {
        accA += __shfl_down_sync(0xFFFFFFFFu, accA, o);
        accB += __shfl_down_sync(0xFFFFFFFFu, accB, o);
    }
    const int wid = tid >> 5, lane = tid & 31;
    if (lane == 0) { redA[wid] = accA; redB[wid] = accB; }
    __syncthreads();
    if (wid == 0) {
        accA = (lane < 16) ? redA[lane] : 0.0f;
        accB = (lane < 16) ? redB[lane] : 0.0f;
#pragma unroll
        for (int o = 8; o > 0; o >>= 1) {
            accA += __shfl_down_sync(0xFFFFFFFFu, accA, o);
            accB += __shfl_down_sync(0xFFFFFFFFu, accB, o);
        }
        if (lane == 0) {
            atomicAdd(&g_accA, (double)accA);
            atomicAdd(&g_accB, (double)accB);
        }
    }
}

__global__ void finalize_kernel(float* __restrict__ out) {
    if (threadIdx.x == 0) out[0] = (float)(g_accA / g_accB);
}

extern "C" void kernel_launch(void* const* d_in, const int* in_sizes, int n_in,
                              void* d_out, int out_size) {
    const float* fake      = (const float*)d_in[0];
    const float* gamma_hdr = (const float*)d_in[1];
    const float* hdr_im    = (const float*)d_in[2];
    const float* r_weights = (const float*)d_in[3];
    const float* f_factors = (const float*)d_in[4];
    const float* gray      = (const float*)d_in[5];
    float* out = (float*)d_out;

    init_kernel<<<1, 32>>>();
    graymax_kernel<<<NB * 64, 256>>>(gray);
    dim3 grid(W_IMG / TILE_W, H_IMG / TILE_H, NB);
    dim3 block(BX, BY);
    intensity_loss_main<<<grid, block>>>(fake, gamma_hdr, hdr_im, r_weights, f_factors);
    finalize_kernel<<<1, 32>>>(out);
}